// round 5
// baseline (speedup 1.0000x reference)
#include <cuda_runtime.h>
#include <math.h>
#include <stdint.h>

#define BB   4
#define CC   384
#define HH   56
#define WW   56
#define HWW  3136
#define NTOK 12544
#define GG   12
#define GCH  32
#define KK2  9
#define OMC  324
#define HID  1536
#define EPSV 1e-5f

// ---------------- scratch (device globals; no allocation) ----------------
__device__ float g_xp [NTOK * CC];
__device__ float g_tn [NTOK * CC];
__device__ float g_val[NTOK * CC];
__device__ float g_om [NTOK * OMC];
__device__ float g_dcn[NTOK * CC];
__device__ float g_res[NTOK * CC];
__device__ float g_ln2[NTOK * CC];
__device__ float g_hid[NTOK * HID];
__device__ float g_fin[NTOK * CC];
__device__ float g_wm [CC * CC];   // om_w zero-padded to [384][384]

// ===================== helpers =====================
__device__ __forceinline__ uint32_t smem_u32(const void* p) {
    uint32_t a;
    asm("{ .reg .u64 t; cvta.to.shared.u64 t, %1; cvt.u32.u64 %0, t; }"
        : "=r"(a) : "l"(p));
    return a;
}
#define CP16(dst, src) \
    asm volatile("cp.async.ca.shared.global [%0], [%1], 16;" \
                 :: "r"(dst), "l"(src))
#define CP_COMMIT() asm volatile("cp.async.commit_group;")
#define CP_WAIT0()  asm volatile("cp.async.wait_group 0;")

#define MMA_TF32(d, a, b) \
    asm volatile("mma.sync.aligned.m16n8k8.row.col.f32.tf32.tf32.f32 " \
        "{%0,%1,%2,%3}, {%4,%5,%6,%7}, {%8,%9}, {%0,%1,%2,%3};" \
        : "+f"((d)[0]), "+f"((d)[1]), "+f"((d)[2]), "+f"((d)[3]) \
        : "r"((a)[0]), "r"((a)[1]), "r"((a)[2]), "r"((a)[3]), \
          "r"((b)[0]), "r"((b)[1]))

// ===================== mma.sync tf32 GEMM =====================
// Out[M,Nn] = A[M,K] @ W[K,N] (+epilogue). W consumed in native [K,Nw] layout.
// CTA tile 128x128, 4 warps (warp tile 64x64), K chunk 16, 2-stage cp.async.
// EPI: 0 = +bias ; 1 = +bias+GELU ; 2 = +bias+Add
#define ASTR 20    // A smem row stride (words): banks 20*g4+tg cover all 32
#define BSTR 132   // B smem row stride (words): banks 132*tg+g4 -> 4*tg+g4

template <int EPI>
__global__ __launch_bounds__(128, 2) void gemm_mma(
    const float* __restrict__ A, const float* __restrict__ W,
    const float* __restrict__ bias, const float* __restrict__ Add,
    float* __restrict__ Out, int Nn, int Nw, int K)
{
    __shared__ float As[2][128][ASTR];
    __shared__ float Bs[2][16][BSTR];

    const int tid  = threadIdx.x;           // 128 threads
    const int lane = tid & 31, warp = tid >> 5;
    const int wm = (warp & 1) * 64, wn = (warp >> 1) * 64;
    const int g4 = lane >> 2, tg = lane & 3;
    const int m0 = blockIdx.x * 128, n0 = blockIdx.y * 128;

    const int brow = tid >> 3;              // 0..15  (B k-row)
    const int bseg = tid & 7;               // 0..7   (B 16-col segment)

    float acc[4][8][4];
#pragma unroll
    for (int a = 0; a < 4; a++)
#pragma unroll
        for (int b = 0; b < 8; b++)
#pragma unroll
            for (int c = 0; c < 4; c++) acc[a][b][c] = 0.f;

    const int nkc = K >> 4;
    const float* srcA = A + (size_t)(m0 + tid) * K;
    const float* srcB = W + (size_t)brow * Nw + n0 + bseg * 16;

#define ISSUE(kc, buf) do {                                               \
        int _k0 = (kc) << 4;                                              \
        _Pragma("unroll")                                                 \
        for (int q = 0; q < 4; q++)                                       \
            CP16(smem_u32(&As[buf][tid][q * 4]), srcA + _k0 + q * 4);     \
        _Pragma("unroll")                                                 \
        for (int q = 0; q < 4; q++)                                       \
            CP16(smem_u32(&Bs[buf][brow][bseg * 16 + q * 4]),             \
                 srcB + (size_t)_k0 * Nw + q * 4);                        \
        CP_COMMIT();                                                      \
    } while (0)

    ISSUE(0, 0);

    for (int kc = 0; kc < nkc; kc++) {
        const int buf = kc & 1;
        CP_WAIT0();
        __syncthreads();
        if (kc + 1 < nkc) ISSUE(kc + 1, buf ^ 1);

#pragma unroll
        for (int s = 0; s < 2; s++) {
            const int ka = s * 8 + tg, kb = ka + 4;
            uint32_t af[4][4], bf[8][2];
#pragma unroll
            for (int mt = 0; mt < 4; mt++) {
                int m = wm + mt * 16 + g4;
                af[mt][0] = __float_as_uint(As[buf][m][ka]);
                af[mt][1] = __float_as_uint(As[buf][m + 8][ka]);
                af[mt][2] = __float_as_uint(As[buf][m][kb]);
                af[mt][3] = __float_as_uint(As[buf][m + 8][kb]);
            }
#pragma unroll
            for (int nt = 0; nt < 8; nt++) {
                int n = wn + nt * 8 + g4;
                bf[nt][0] = __float_as_uint(Bs[buf][ka][n]);
                bf[nt][1] = __float_as_uint(Bs[buf][kb][n]);
            }
#pragma unroll
            for (int mt = 0; mt < 4; mt++)
#pragma unroll
                for (int nt = 0; nt < 8; nt++)
                    MMA_TF32(acc[mt][nt], af[mt], bf[nt]);
        }
    }
#undef ISSUE

    // epilogue
#pragma unroll
    for (int mt = 0; mt < 4; mt++) {
        int row = m0 + wm + mt * 16 + g4;
#pragma unroll
        for (int nt = 0; nt < 8; nt++) {
            int col = n0 + wn + nt * 8 + tg * 2;
            if (col < Nn) {
                float b0 = __ldg(&bias[col]), b1 = __ldg(&bias[col + 1]);
                float v0 = acc[mt][nt][0] + b0;
                float v1 = acc[mt][nt][1] + b1;
                float v2 = acc[mt][nt][2] + b0;
                float v3 = acc[mt][nt][3] + b1;
                if (EPI == 1) {
                    v0 = 0.5f * v0 * (1.f + erff(v0 * 0.70710678118654752f));
                    v1 = 0.5f * v1 * (1.f + erff(v1 * 0.70710678118654752f));
                    v2 = 0.5f * v2 * (1.f + erff(v2 * 0.70710678118654752f));
                    v3 = 0.5f * v3 * (1.f + erff(v3 * 0.70710678118654752f));
                }
                if (EPI == 2) {
                    v0 += Add[(size_t)row * Nn + col];
                    v1 += Add[(size_t)row * Nn + col + 1];
                    v2 += Add[(size_t)(row + 8) * Nn + col];
                    v3 += Add[(size_t)(row + 8) * Nn + col + 1];
                }
                *reinterpret_cast<float2*>(Out + (size_t)row * Nn + col)       = make_float2(v0, v1);
                *reinterpret_cast<float2*>(Out + (size_t)(row + 8) * Nn + col) = make_float2(v2, v3);
            }
        }
    }
}

// ---------------- pad om_w [384][324] -> [384][384] (zeros) ---------------
__global__ void pad_om(const float* __restrict__ src, float* __restrict__ dst)
{
    int k = blockIdx.x, n = threadIdx.x;     // 384 x 384
    dst[k * CC + n] = (n < OMC) ? src[k * OMC + n] : 0.f;
}

// ---------------- LN1: transpose x + layernorm ----------------
__global__ void ln1_kernel(const float* __restrict__ x,
                           const float* __restrict__ gam,
                           const float* __restrict__ bet,
                           float* __restrict__ xp, float* __restrict__ tn)
{
    int warp = (blockIdx.x * blockDim.x + threadIdx.x) >> 5;
    if (warp >= NTOK) return;
    int lane = threadIdx.x & 31;
    int b  = warp / HWW;
    int hw = warp - b * HWW;
    const float* xb = x + (size_t)b * CC * HWW + hw;

    float v[12];
#pragma unroll
    for (int i = 0; i < 12; i++) v[i] = xb[(size_t)(lane + 32 * i) * HWW];
    float s = 0.f;
#pragma unroll
    for (int i = 0; i < 12; i++) s += v[i];
#pragma unroll
    for (int o = 16; o; o >>= 1) s += __shfl_xor_sync(0xffffffffu, s, o);
    float mu = s * (1.0f / CC);
    float q = 0.f;
#pragma unroll
    for (int i = 0; i < 12; i++) { float d = v[i] - mu; q += d * d; }
#pragma unroll
    for (int o = 16; o; o >>= 1) q += __shfl_xor_sync(0xffffffffu, q, o);
    float rs = rsqrtf(q * (1.0f / CC) + EPSV);
    size_t base = (size_t)warp * CC;
#pragma unroll
    for (int i = 0; i < 12; i++) {
        int c = lane + 32 * i;
        xp[base + c] = v[i];
        tn[base + c] = (v[i] - mu) * rs * gam[c] + bet[c];
    }
}

__global__ void ln2_kernel(const float* __restrict__ res,
                           const float* __restrict__ gam,
                           const float* __restrict__ bet,
                           float* __restrict__ outp)
{
    int warp = (blockIdx.x * blockDim.x + threadIdx.x) >> 5;
    if (warp >= NTOK) return;
    int lane = threadIdx.x & 31;
    size_t base = (size_t)warp * CC;
    float v[12];
#pragma unroll
    for (int i = 0; i < 12; i++) v[i] = res[base + lane + 32 * i];
    float s = 0.f;
#pragma unroll
    for (int i = 0; i < 12; i++) s += v[i];
#pragma unroll
    for (int o = 16; o; o >>= 1) s += __shfl_xor_sync(0xffffffffu, s, o);
    float mu = s * (1.0f / CC);
    float q = 0.f;
#pragma unroll
    for (int i = 0; i < 12; i++) { float d = v[i] - mu; q += d * d; }
#pragma unroll
    for (int o = 16; o; o >>= 1) q += __shfl_xor_sync(0xffffffffu, q, o);
    float rs = rsqrtf(q * (1.0f / CC) + EPSV);
#pragma unroll
    for (int i = 0; i < 12; i++) {
        int c = lane + 32 * i;
        outp[base + c] = (v[i] - mu) * rs * gam[c] + bet[c];
    }
}

// ---------------- DCNv4 sampling: one block per token, warp = group -------
__global__ __launch_bounds__(384) void dcn_kernel(
    const float* __restrict__ val,
    const float* __restrict__ om,
    float* __restrict__ outp)
{
    __shared__ float s_om[OMC];
    const int n = blockIdx.x;
    const int tid = threadIdx.x;
    if (tid < OMC) s_om[tid] = om[(size_t)n * OMC + tid];
    __syncthreads();

    const int g = tid >> 5, lane = tid & 31;
    const int b = n / HWW;
    const int hw = n - b * HWW;
    const int ii = hw / WW;
    const int jj = hw - ii * WW;

    const float* omb = s_om + g * 27;
    const float* vb  = val + b * (HWW * CC) + g * GCH + lane;

    float acc = 0.f;
#pragma unroll
    for (int k = 0; k < KK2; k++) {
        float dx = omb[2 * k];
        float dy = omb[2 * k + 1];
        float mk = omb[18 + k];
        float px = (float)jj + (float)(k % 3 - 1) + dx;
        float py = (float)ii + (float)(k / 3 - 1) + dy;
        float x0f = floorf(px), y0f = floorf(py);
        float tx = px - x0f, ty = py - y0f;
        int x0 = (int)x0f, y0 = (int)y0f;
        int x1 = x0 + 1,   y1 = y0 + 1;
        bool vx0 = (x0 >= 0) & (x0 < WW);
        bool vx1 = (x1 >= 0) & (x1 < WW);
        bool vy0 = (y0 >= 0) & (y0 < HH);
        bool vy1 = (y1 >= 0) & (y1 < HH);
        int row0 = y0 * (WW * CC), row1 = row0 + WW * CC;
        float v00 = (vy0 && vx0) ? __ldg(vb + row0 + x0 * CC) : 0.f;
        float v01 = (vy0 && vx1) ? __ldg(vb + row0 + x1 * CC) : 0.f;
        float v10 = (vy1 && vx0) ? __ldg(vb + row1 + x0 * CC) : 0.f;
        float v11 = (vy1 && vx1) ? __ldg(vb + row1 + x1 * CC) : 0.f;
        float top = v00 * (1.f - tx) + v01 * tx;
        float bot = v10 * (1.f - tx) + v11 * tx;
        acc += mk * (top * (1.f - ty) + bot * ty);
    }
    outp[n * CC + g * GCH + lane] = acc;
}

// ---------------- final transpose ----------------
__global__ void transpose_out(const float* __restrict__ fin,
                              float* __restrict__ outp)
{
    __shared__ float s[32][33];
    int b   = blockIdx.z;
    int hw0 = blockIdx.x * 32;
    int c0  = blockIdx.y * 32;
    int tx = threadIdx.x, ty = threadIdx.y;
#pragma unroll
    for (int r = 0; r < 4; r++) {
        int hw = hw0 + ty + 8 * r;
        s[ty + 8 * r][tx] = fin[(size_t)(b * HWW + hw) * CC + c0 + tx];
    }
    __syncthreads();
#pragma unroll
    for (int r = 0; r < 4; r++) {
        int c = c0 + ty + 8 * r;
        outp[(size_t)(b * CC + c) * HWW + hw0 + tx] = s[tx][ty + 8 * r];
    }
}

// --------------------------------------------------------------------------
extern "C" void kernel_launch(void* const* d_in, const int* in_sizes, int n_in,
                              void* d_out, int out_size)
{
    const float* x       = (const float*)d_in[0];
    const float* ln1_g   = (const float*)d_in[1];
    const float* ln1_b   = (const float*)d_in[2];
    const float* vproj_w = (const float*)d_in[3];
    const float* vproj_b = (const float*)d_in[4];
    const float* om_w    = (const float*)d_in[5];
    const float* om_b    = (const float*)d_in[6];
    const float* oproj_w = (const float*)d_in[7];
    const float* oproj_b = (const float*)d_in[8];
    const float* ln2_g   = (const float*)d_in[9];
    const float* ln2_b   = (const float*)d_in[10];
    const float* fc1_w   = (const float*)d_in[11];
    const float* fc1_b   = (const float*)d_in[12];
    const float* fc2_w   = (const float*)d_in[13];
    const float* fc2_b   = (const float*)d_in[14];
    float* outp = (float*)d_out;

    float *xp, *tn, *val, *om, *dcn, *res, *ln2o, *hid, *fin, *wm;
    cudaGetSymbolAddress((void**)&xp,  g_xp);
    cudaGetSymbolAddress((void**)&tn,  g_tn);
    cudaGetSymbolAddress((void**)&val, g_val);
    cudaGetSymbolAddress((void**)&om,  g_om);
    cudaGetSymbolAddress((void**)&dcn, g_dcn);
    cudaGetSymbolAddress((void**)&res, g_res);
    cudaGetSymbolAddress((void**)&ln2o, g_ln2);
    cudaGetSymbolAddress((void**)&hid, g_hid);
    cudaGetSymbolAddress((void**)&fin, g_fin);
    cudaGetSymbolAddress((void**)&wm,  g_wm);

    // pad om_w to [384][384]
    pad_om<<<CC, CC>>>(om_w, wm);
    // 1. transpose + LN1
    ln1_kernel<<<NTOK / 8, 256>>>(x, ln1_g, ln1_b, xp, tn);
    // 2. val = tn @ vproj_w + b
    gemm_mma<0><<<dim3(NTOK / 128, 3), 128>>>(tn, vproj_w, vproj_b, nullptr, val, CC, CC, CC);
    // 3. om = tn @ om_w + b (padded W, Nn=324)
    gemm_mma<0><<<dim3(NTOK / 128, 3), 128>>>(tn, wm, om_b, nullptr, om, OMC, CC, CC);
    // 4. DCN sampling
    dcn_kernel<<<NTOK, 384>>>(val, om, dcn);
    // 5. res = xp + dcn @ oproj_w + b
    gemm_mma<2><<<dim3(NTOK / 128, 3), 128>>>(dcn, oproj_w, oproj_b, xp, res, CC, CC, CC);
    // 6. LN2
    ln2_kernel<<<NTOK / 8, 256>>>(res, ln2_g, ln2_b, ln2o);
    // 7. hid = gelu(ln2o @ fc1_w + b)
    gemm_mma<1><<<dim3(NTOK / 128, HID / 128), 128>>>(ln2o, fc1_w, fc1_b, nullptr, hid, HID, HID, CC);
    // 8. fin = res + hid @ fc2_w + b
    gemm_mma<2><<<dim3(NTOK / 128, 3), 128>>>(hid, fc2_w, fc2_b, res, fin, CC, CC, HID);
    // 9. transpose back
    transpose_out<<<dim3(HWW / 32, CC / 32, BB), dim3(32, 8)>>>(fin, outp);
}

// round 6
// speedup vs baseline: 1.1127x; 1.1127x over previous
#include <cuda_runtime.h>
#include <math.h>
#include <stdint.h>

#define BB   4
#define CC   384
#define HH   56
#define WW   56
#define HWW  3136
#define NTOK 12544
#define GG   12
#define GCH  32
#define KK2  9
#define OMC  324
#define HID  1536
#define EPSV 1e-5f

// ---------------- scratch (device globals; no allocation) ----------------
__device__ float g_xp [NTOK * CC];
__device__ float g_tn [NTOK * CC];
__device__ float g_val[NTOK * CC];
__device__ float g_om [NTOK * OMC];
__device__ float g_dcn[NTOK * CC];
__device__ float g_res[NTOK * CC];
__device__ float g_ln2[NTOK * CC];
__device__ float g_hid[NTOK * HID];
__device__ float g_fin[NTOK * CC];
__device__ float g_wm [CC * CC];   // om_w zero-padded to [384][384]

// ===================== helpers =====================
__device__ __forceinline__ uint32_t smem_u32(const void* p) {
    uint32_t a;
    asm("{ .reg .u64 t; cvta.to.shared.u64 t, %1; cvt.u32.u64 %0, t; }"
        : "=r"(a) : "l"(p));
    return a;
}
#define CP16(dst, src) \
    asm volatile("cp.async.ca.shared.global [%0], [%1], 16;" \
                 :: "r"(dst), "l"(src))
#define CP_COMMIT() asm volatile("cp.async.commit_group;")
#define CP_WAIT0()  asm volatile("cp.async.wait_group 0;")

#define MMA_TF32(d, a, b) \
    asm volatile("mma.sync.aligned.m16n8k8.row.col.f32.tf32.tf32.f32 " \
        "{%0,%1,%2,%3}, {%4,%5,%6,%7}, {%8,%9}, {%0,%1,%2,%3};" \
        : "+f"((d)[0]), "+f"((d)[1]), "+f"((d)[2]), "+f"((d)[3]) \
        : "r"((a)[0]), "r"((a)[1]), "r"((a)[2]), "r"((a)[3]), \
          "r"((b)[0]), "r"((b)[1]))

// ===================== mma.sync tf32 GEMM =====================
// Out[M,Nn] = A[M,K] @ W[K,Nw] (+epilogue). W consumed in native [K,Nw] layout.
// CTA tile 128x128, 8 warps (warp tile 64x32), K chunk 16, 2-stage cp.async.
// EPI: 0 = +bias ; 1 = +bias+GELU ; 2 = +bias+Add
#define ASTR 20    // A smem row stride (words): banks 20*g4+tg cover all 32
#define BSTR 132   // B smem row stride (words): banks (132*k + n) mod 32 distinct per lane

template <int EPI>
__global__ __launch_bounds__(256, 2) void gemm_mma(
    const float* __restrict__ A, const float* __restrict__ W,
    const float* __restrict__ bias, const float* __restrict__ Add,
    float* __restrict__ Out, int Nn, int Nw, int K)
{
    __shared__ float As[2][128][ASTR];
    __shared__ float Bs[2][16][BSTR];

    const int tid  = threadIdx.x;           // 256 threads
    const int lane = tid & 31, warp = tid >> 5;
    const int wm = (warp >> 2) * 64, wn = (warp & 3) * 32;
    const int g4 = lane >> 2, tg = lane & 3;
    const int m0 = blockIdx.x * 128, n0 = blockIdx.y * 128;

    const int ar = tid >> 1;                // 0..127 (A row)
    const int aq = tid & 1;                 // A quad selector
    const int brow = tid >> 4;              // 0..15  (B k-row)
    const int bseg = tid & 15;              // 0..15  (B quad segment)

    float acc[4][4][4];
#pragma unroll
    for (int a = 0; a < 4; a++)
#pragma unroll
        for (int b = 0; b < 4; b++)
#pragma unroll
            for (int c = 0; c < 4; c++) acc[a][b][c] = 0.f;

    const int nkc = K >> 4;
    const float* srcA = A + (size_t)(m0 + ar) * K;
    const float* srcB = W + (size_t)brow * Nw + n0;

#define ISSUE(kc, buf) do {                                                  \
        int _k0 = (kc) << 4;                                                 \
        CP16(smem_u32(&As[buf][ar][aq * 4]),     srcA + _k0 + aq * 4);       \
        CP16(smem_u32(&As[buf][ar][aq * 4 + 8]), srcA + _k0 + aq * 4 + 8);   \
        CP16(smem_u32(&Bs[buf][brow][bseg * 4]),                             \
             srcB + (size_t)_k0 * Nw + bseg * 4);                            \
        CP16(smem_u32(&Bs[buf][brow][bseg * 4 + 64]),                        \
             srcB + (size_t)_k0 * Nw + bseg * 4 + 64);                       \
        CP_COMMIT();                                                         \
    } while (0)

    ISSUE(0, 0);

    for (int kc = 0; kc < nkc; kc++) {
        const int buf = kc & 1;
        CP_WAIT0();
        __syncthreads();
        if (kc + 1 < nkc) ISSUE(kc + 1, buf ^ 1);

#pragma unroll
        for (int s = 0; s < 2; s++) {
            const int ka = s * 8 + tg, kb = ka + 4;
            uint32_t af[4][4], bf[4][2];
#pragma unroll
            for (int mt = 0; mt < 4; mt++) {
                int m = wm + mt * 16 + g4;
                af[mt][0] = __float_as_uint(As[buf][m][ka]);
                af[mt][1] = __float_as_uint(As[buf][m + 8][ka]);
                af[mt][2] = __float_as_uint(As[buf][m][kb]);
                af[mt][3] = __float_as_uint(As[buf][m + 8][kb]);
            }
#pragma unroll
            for (int nt = 0; nt < 4; nt++) {
                int n = wn + nt * 8 + g4;
                bf[nt][0] = __float_as_uint(Bs[buf][ka][n]);
                bf[nt][1] = __float_as_uint(Bs[buf][kb][n]);
            }
#pragma unroll
            for (int mt = 0; mt < 4; mt++)
#pragma unroll
                for (int nt = 0; nt < 4; nt++)
                    MMA_TF32(acc[mt][nt], af[mt], bf[nt]);
        }
    }
#undef ISSUE

    // epilogue
#pragma unroll
    for (int mt = 0; mt < 4; mt++) {
        int row = m0 + wm + mt * 16 + g4;
#pragma unroll
        for (int nt = 0; nt < 4; nt++) {
            int col = n0 + wn + nt * 8 + tg * 2;
            if (col < Nn) {
                float b0 = __ldg(&bias[col]), b1 = __ldg(&bias[col + 1]);
                float v0 = acc[mt][nt][0] + b0;
                float v1 = acc[mt][nt][1] + b1;
                float v2 = acc[mt][nt][2] + b0;
                float v3 = acc[mt][nt][3] + b1;
                if (EPI == 1) {
                    v0 = 0.5f * v0 * (1.f + erff(v0 * 0.70710678118654752f));
                    v1 = 0.5f * v1 * (1.f + erff(v1 * 0.70710678118654752f));
                    v2 = 0.5f * v2 * (1.f + erff(v2 * 0.70710678118654752f));
                    v3 = 0.5f * v3 * (1.f + erff(v3 * 0.70710678118654752f));
                }
                if (EPI == 2) {
                    v0 += Add[(size_t)row * Nn + col];
                    v1 += Add[(size_t)row * Nn + col + 1];
                    v2 += Add[(size_t)(row + 8) * Nn + col];
                    v3 += Add[(size_t)(row + 8) * Nn + col + 1];
                }
                *reinterpret_cast<float2*>(Out + (size_t)row * Nn + col)       = make_float2(v0, v1);
                *reinterpret_cast<float2*>(Out + (size_t)(row + 8) * Nn + col) = make_float2(v2, v3);
            }
        }
    }
}

// ---------------- pad om_w [384][324] -> [384][384] (zeros) ---------------
__global__ void pad_om(const float* __restrict__ src, float* __restrict__ dst)
{
    int k = blockIdx.x, n = threadIdx.x;     // 384 x 384
    dst[k * CC + n] = (n < OMC) ? src[k * OMC + n] : 0.f;
}

// ---------------- LN1: transpose x + layernorm ----------------
__global__ void ln1_kernel(const float* __restrict__ x,
                           const float* __restrict__ gam,
                           const float* __restrict__ bet,
                           float* __restrict__ xp, float* __restrict__ tn)
{
    int warp = (blockIdx.x * blockDim.x + threadIdx.x) >> 5;
    if (warp >= NTOK) return;
    int lane = threadIdx.x & 31;
    int b  = warp / HWW;
    int hw = warp - b * HWW;
    const float* xb = x + (size_t)b * CC * HWW + hw;

    float v[12];
#pragma unroll
    for (int i = 0; i < 12; i++) v[i] = xb[(size_t)(lane + 32 * i) * HWW];
    float s = 0.f;
#pragma unroll
    for (int i = 0; i < 12; i++) s += v[i];
#pragma unroll
    for (int o = 16; o; o >>= 1) s += __shfl_xor_sync(0xffffffffu, s, o);
    float mu = s * (1.0f / CC);
    float q = 0.f;
#pragma unroll
    for (int i = 0; i < 12; i++) { float d = v[i] - mu; q += d * d; }
#pragma unroll
    for (int o = 16; o; o >>= 1) q += __shfl_xor_sync(0xffffffffu, q, o);
    float rs = rsqrtf(q * (1.0f / CC) + EPSV);
    size_t base = (size_t)warp * CC;
#pragma unroll
    for (int i = 0; i < 12; i++) {
        int c = lane + 32 * i;
        xp[base + c] = v[i];
        tn[base + c] = (v[i] - mu) * rs * gam[c] + bet[c];
    }
}

__global__ void ln2_kernel(const float* __restrict__ res,
                           const float* __restrict__ gam,
                           const float* __restrict__ bet,
                           float* __restrict__ outp)
{
    int warp = (blockIdx.x * blockDim.x + threadIdx.x) >> 5;
    if (warp >= NTOK) return;
    int lane = threadIdx.x & 31;
    size_t base = (size_t)warp * CC;
    float v[12];
#pragma unroll
    for (int i = 0; i < 12; i++) v[i] = res[base + lane + 32 * i];
    float s = 0.f;
#pragma unroll
    for (int i = 0; i < 12; i++) s += v[i];
#pragma unroll
    for (int o = 16; o; o >>= 1) s += __shfl_xor_sync(0xffffffffu, s, o);
    float mu = s * (1.0f / CC);
    float q = 0.f;
#pragma unroll
    for (int i = 0; i < 12; i++) { float d = v[i] - mu; q += d * d; }
#pragma unroll
    for (int o = 16; o; o >>= 1) q += __shfl_xor_sync(0xffffffffu, q, o);
    float rs = rsqrtf(q * (1.0f / CC) + EPSV);
#pragma unroll
    for (int i = 0; i < 12; i++) {
        int c = lane + 32 * i;
        outp[base + c] = (v[i] - mu) * rs * gam[c] + bet[c];
    }
}

// ---------------- DCNv4 sampling: one block per token, warp = group -------
__global__ __launch_bounds__(384) void dcn_kernel(
    const float* __restrict__ val,
    const float* __restrict__ om,
    float* __restrict__ outp)
{
    __shared__ float s_om[OMC];
    const int n = blockIdx.x;
    const int tid = threadIdx.x;
    if (tid < OMC) s_om[tid] = om[(size_t)n * OMC + tid];
    __syncthreads();

    const int g = tid >> 5, lane = tid & 31;
    const int b = n / HWW;
    const int hw = n - b * HWW;
    const int ii = hw / WW;
    const int jj = hw - ii * WW;

    const float* omb = s_om + g * 27;
    const float* vb  = val + b * (HWW * CC) + g * GCH + lane;

    float acc = 0.f;
#pragma unroll
    for (int k = 0; k < KK2; k++) {
        float dx = omb[2 * k];
        float dy = omb[2 * k + 1];
        float mk = omb[18 + k];
        float px = (float)jj + (float)(k % 3 - 1) + dx;
        float py = (float)ii + (float)(k / 3 - 1) + dy;
        float x0f = floorf(px), y0f = floorf(py);
        float tx = px - x0f, ty = py - y0f;
        int x0 = (int)x0f, y0 = (int)y0f;
        int x1 = x0 + 1,   y1 = y0 + 1;
        bool vx0 = (x0 >= 0) & (x0 < WW);
        bool vx1 = (x1 >= 0) & (x1 < WW);
        bool vy0 = (y0 >= 0) & (y0 < HH);
        bool vy1 = (y1 >= 0) & (y1 < HH);
        int row0 = y0 * (WW * CC), row1 = row0 + WW * CC;
        float v00 = (vy0 && vx0) ? __ldg(vb + row0 + x0 * CC) : 0.f;
        float v01 = (vy0 && vx1) ? __ldg(vb + row0 + x1 * CC) : 0.f;
        float v10 = (vy1 && vx0) ? __ldg(vb + row1 + x0 * CC) : 0.f;
        float v11 = (vy1 && vx1) ? __ldg(vb + row1 + x1 * CC) : 0.f;
        float top = v00 * (1.f - tx) + v01 * tx;
        float bot = v10 * (1.f - tx) + v11 * tx;
        acc += mk * (top * (1.f - ty) + bot * ty);
    }
    outp[n * CC + g * GCH + lane] = acc;
}

// ---------------- final transpose ----------------
__global__ void transpose_out(const float* __restrict__ fin,
                              float* __restrict__ outp)
{
    __shared__ float s[32][33];
    int b   = blockIdx.z;
    int hw0 = blockIdx.x * 32;
    int c0  = blockIdx.y * 32;
    int tx = threadIdx.x, ty = threadIdx.y;
#pragma unroll
    for (int r = 0; r < 4; r++) {
        int hw = hw0 + ty + 8 * r;
        s[ty + 8 * r][tx] = fin[(size_t)(b * HWW + hw) * CC + c0 + tx];
    }
    __syncthreads();
#pragma unroll
    for (int r = 0; r < 4; r++) {
        int c = c0 + ty + 8 * r;
        outp[(size_t)(b * CC + c) * HWW + hw0 + tx] = s[tx][ty + 8 * r];
    }
}

// --------------------------------------------------------------------------
extern "C" void kernel_launch(void* const* d_in, const int* in_sizes, int n_in,
                              void* d_out, int out_size)
{
    const float* x       = (const float*)d_in[0];
    const float* ln1_g   = (const float*)d_in[1];
    const float* ln1_b   = (const float*)d_in[2];
    const float* vproj_w = (const float*)d_in[3];
    const float* vproj_b = (const float*)d_in[4];
    const float* om_w    = (const float*)d_in[5];
    const float* om_b    = (const float*)d_in[6];
    const float* oproj_w = (const float*)d_in[7];
    const float* oproj_b = (const float*)d_in[8];
    const float* ln2_g   = (const float*)d_in[9];
    const float* ln2_b   = (const float*)d_in[10];
    const float* fc1_w   = (const float*)d_in[11];
    const float* fc1_b   = (const float*)d_in[12];
    const float* fc2_w   = (const float*)d_in[13];
    const float* fc2_b   = (const float*)d_in[14];
    float* outp = (float*)d_out;

    float *xp, *tn, *val, *om, *dcn, *res, *ln2o, *hid, *fin, *wm;
    cudaGetSymbolAddress((void**)&xp,  g_xp);
    cudaGetSymbolAddress((void**)&tn,  g_tn);
    cudaGetSymbolAddress((void**)&val, g_val);
    cudaGetSymbolAddress((void**)&om,  g_om);
    cudaGetSymbolAddress((void**)&dcn, g_dcn);
    cudaGetSymbolAddress((void**)&res, g_res);
    cudaGetSymbolAddress((void**)&ln2o, g_ln2);
    cudaGetSymbolAddress((void**)&hid, g_hid);
    cudaGetSymbolAddress((void**)&fin, g_fin);
    cudaGetSymbolAddress((void**)&wm,  g_wm);

    // pad om_w to [384][384]
    pad_om<<<CC, CC>>>(om_w, wm);
    // 1. transpose + LN1
    ln1_kernel<<<NTOK / 8, 256>>>(x, ln1_g, ln1_b, xp, tn);
    // 2. val = tn @ vproj_w + b
    gemm_mma<0><<<dim3(NTOK / 128, 3), 256>>>(tn, vproj_w, vproj_b, nullptr, val, CC, CC, CC);
    // 3. om = tn @ om_w + b (padded W, Nn=324)
    gemm_mma<0><<<dim3(NTOK / 128, 3), 256>>>(tn, wm, om_b, nullptr, om, OMC, CC, CC);
    // 4. DCN sampling
    dcn_kernel<<<NTOK, 384>>>(val, om, dcn);
    // 5. res = xp + dcn @ oproj_w + b
    gemm_mma<2><<<dim3(NTOK / 128, 3), 256>>>(dcn, oproj_w, oproj_b, xp, res, CC, CC, CC);
    // 6. LN2
    ln2_kernel<<<NTOK / 8, 256>>>(res, ln2_g, ln2_b, ln2o);
    // 7. hid = gelu(ln2o @ fc1_w + b)
    gemm_mma<1><<<dim3(NTOK / 128, HID / 128), 256>>>(ln2o, fc1_w, fc1_b, nullptr, hid, HID, HID, CC);
    // 8. fin = res + hid @ fc2_w + b
    gemm_mma<2><<<dim3(NTOK / 128, 3), 256>>>(hid, fc2_w, fc2_b, res, fin, CC, CC, HID);
    // 9. transpose back
    transpose_out<<<dim3(HWW / 32, CC / 32, BB), dim3(32, 8)>>>(fin, outp);
}

// round 7
// speedup vs baseline: 1.1703x; 1.0518x over previous
#include <cuda_runtime.h>
#include <math.h>
#include <stdint.h>

#define BB   4
#define CC   384
#define HH   56
#define WW   56
#define HWW  3136
#define NTOK 12544
#define GG   12
#define GCH  32
#define KK2  9
#define OMC  324
#define HID  1536
#define EPSV 1e-5f

// ---------------- scratch (device globals; no allocation) ----------------
__device__ float g_xp [NTOK * CC];
__device__ float g_tn [NTOK * CC];
__device__ float g_val[NTOK * CC];
__device__ float g_om [NTOK * OMC];
__device__ float g_dcn[NTOK * CC];
__device__ float g_res[NTOK * CC];
__device__ float g_ln2[NTOK * CC];
__device__ float g_hid[NTOK * HID];
__device__ float g_fin[NTOK * CC];
__device__ float g_wm [CC * CC];   // om_w zero-padded to [384][384]

// ===================== helpers =====================
__device__ __forceinline__ uint32_t smem_u32(const void* p) {
    uint32_t a;
    asm("{ .reg .u64 t; cvta.to.shared.u64 t, %1; cvt.u32.u64 %0, t; }"
        : "=r"(a) : "l"(p));
    return a;
}
#define CP16(dst, src) \
    asm volatile("cp.async.ca.shared.global [%0], [%1], 16;" \
                 :: "r"(dst), "l"(src))
#define CP_COMMIT() asm volatile("cp.async.commit_group;")
#define CP_WAIT1()  asm volatile("cp.async.wait_group 1;")
#define CP_WAIT0()  asm volatile("cp.async.wait_group 0;")

#define MMA_TF32(d, a, b) \
    asm volatile("mma.sync.aligned.m16n8k8.row.col.f32.tf32.tf32.f32 " \
        "{%0,%1,%2,%3}, {%4,%5,%6,%7}, {%8,%9}, {%0,%1,%2,%3};" \
        : "+f"((d)[0]), "+f"((d)[1]), "+f"((d)[2]), "+f"((d)[3]) \
        : "r"((a)[0]), "r"((a)[1]), "r"((a)[2]), "r"((a)[3]), \
          "r"((b)[0]), "r"((b)[1]))

// ===================== mma.sync tf32 GEMM =====================
// Out[M,Nn] = A[M,K] @ W[K,Nw] (+epilogue). W consumed in native [K,Nw] layout.
// CTA tile 128x128, 8 warps (warp tile 64x32), K chunk 16, 3-stage cp.async.
// EPI: 0 = +bias ; 1 = +bias+GELU ; 2 = +bias+Add
#define ASTR 20    // A smem row stride (words): banks 20*g4+tg cover all 32
#define BSTR 136   // B smem row stride (words): 136%32=8 -> bank 8*tg+g4, all distinct
#define A_FLOATS (128 * ASTR)
#define B_FLOATS (16 * BSTR)
#define GEMM_SMEM_BYTES ((3 * (A_FLOATS + B_FLOATS)) * 4)

template <int EPI>
__global__ __launch_bounds__(256, 2) void gemm_mma(
    const float* __restrict__ A, const float* __restrict__ W,
    const float* __restrict__ bias, const float* __restrict__ Add,
    float* __restrict__ Out, int Nn, int Nw, int K)
{
    extern __shared__ float dyn[];
    float* Asb = dyn;                       // [3][128][ASTR]
    float* Bsb = dyn + 3 * A_FLOATS;        // [3][16][BSTR]

    const int tid  = threadIdx.x;           // 256 threads
    const int lane = tid & 31, warp = tid >> 5;
    const int wm = (warp >> 2) * 64, wn = (warp & 3) * 32;
    const int g4 = lane >> 2, tg = lane & 3;
    const int m0 = blockIdx.x * 128, n0 = blockIdx.y * 128;

    const int ar = tid >> 1;                // 0..127 (A row)
    const int aq = tid & 1;                 // A quad selector
    const int brow = tid >> 4;              // 0..15  (B k-row)
    const int bseg = tid & 15;              // 0..15  (B quad segment)

    float acc[4][4][4];
#pragma unroll
    for (int a = 0; a < 4; a++)
#pragma unroll
        for (int b = 0; b < 4; b++)
#pragma unroll
            for (int c = 0; c < 4; c++) acc[a][b][c] = 0.f;

    const int nkc = K >> 4;
    const float* srcA = A + (size_t)(m0 + ar) * K;
    const float* srcB = W + (size_t)brow * Nw + n0;

#define ISSUE(kc, buf) do {                                                   \
        int _k0 = (kc) << 4;                                                  \
        float* _As = Asb + (buf) * A_FLOATS + ar * ASTR;                      \
        float* _Bs = Bsb + (buf) * B_FLOATS + brow * BSTR;                    \
        CP16(smem_u32(_As + aq * 4),     srcA + _k0 + aq * 4);                \
        CP16(smem_u32(_As + aq * 4 + 8), srcA + _k0 + aq * 4 + 8);            \
        CP16(smem_u32(_Bs + bseg * 4),                                        \
             srcB + (size_t)_k0 * Nw + bseg * 4);                             \
        CP16(smem_u32(_Bs + bseg * 4 + 64),                                   \
             srcB + (size_t)_k0 * Nw + bseg * 4 + 64);                        \
        CP_COMMIT();                                                          \
    } while (0)

    ISSUE(0, 0);
    ISSUE(1, 1);

    int buf = 0;
    for (int kc = 0; kc < nkc; kc++) {
        if (kc + 2 < nkc) CP_WAIT1(); else CP_WAIT0();
        __syncthreads();
        if (kc + 2 < nkc) {
            int nb = buf; // (kc+2)%3 == buf of (kc-1), free after the sync above
            nb = kc + 2 - ((kc + 2) / 3) * 3;
            ISSUE(kc + 2, nb);
        }
        const float* As = Asb + buf * A_FLOATS;
        const float* Bs = Bsb + buf * B_FLOATS;

#pragma unroll
        for (int s = 0; s < 2; s++) {
            const int ka = s * 8 + tg, kb = ka + 4;
            uint32_t af[4][4], bf[4][2];
#pragma unroll
            for (int mt = 0; mt < 4; mt++) {
                int m = wm + mt * 16 + g4;
                af[mt][0] = __float_as_uint(As[m * ASTR + ka]);
                af[mt][1] = __float_as_uint(As[(m + 8) * ASTR + ka]);
                af[mt][2] = __float_as_uint(As[m * ASTR + kb]);
                af[mt][3] = __float_as_uint(As[(m + 8) * ASTR + kb]);
            }
#pragma unroll
            for (int nt = 0; nt < 4; nt++) {
                int n = wn + nt * 8 + g4;
                bf[nt][0] = __float_as_uint(Bs[ka * BSTR + n]);
                bf[nt][1] = __float_as_uint(Bs[kb * BSTR + n]);
            }
#pragma unroll
            for (int mt = 0; mt < 4; mt++)
#pragma unroll
                for (int nt = 0; nt < 4; nt++)
                    MMA_TF32(acc[mt][nt], af[mt], bf[nt]);
        }
        buf++; if (buf == 3) buf = 0;
    }
#undef ISSUE

    // epilogue
#pragma unroll
    for (int mt = 0; mt < 4; mt++) {
        int row = m0 + wm + mt * 16 + g4;
#pragma unroll
        for (int nt = 0; nt < 4; nt++) {
            int col = n0 + wn + nt * 8 + tg * 2;
            if (col < Nn) {
                float b0 = __ldg(&bias[col]), b1 = __ldg(&bias[col + 1]);
                float v0 = acc[mt][nt][0] + b0;
                float v1 = acc[mt][nt][1] + b1;
                float v2 = acc[mt][nt][2] + b0;
                float v3 = acc[mt][nt][3] + b1;
                if (EPI == 1) {
                    v0 = 0.5f * v0 * (1.f + erff(v0 * 0.70710678118654752f));
                    v1 = 0.5f * v1 * (1.f + erff(v1 * 0.70710678118654752f));
                    v2 = 0.5f * v2 * (1.f + erff(v2 * 0.70710678118654752f));
                    v3 = 0.5f * v3 * (1.f + erff(v3 * 0.70710678118654752f));
                }
                if (EPI == 2) {
                    v0 += Add[(size_t)row * Nn + col];
                    v1 += Add[(size_t)row * Nn + col + 1];
                    v2 += Add[(size_t)(row + 8) * Nn + col];
                    v3 += Add[(size_t)(row + 8) * Nn + col + 1];
                }
                *reinterpret_cast<float2*>(Out + (size_t)row * Nn + col)       = make_float2(v0, v1);
                *reinterpret_cast<float2*>(Out + (size_t)(row + 8) * Nn + col) = make_float2(v2, v3);
            }
        }
    }
}

// ---------------- pad om_w [384][324] -> [384][384] (zeros) ---------------
__global__ void pad_om(const float* __restrict__ src, float* __restrict__ dst)
{
    int k = blockIdx.x, n = threadIdx.x;     // 384 x 384
    dst[k * CC + n] = (n < OMC) ? src[k * OMC + n] : 0.f;
}

// ---------------- LN1: transpose x + layernorm ----------------
__global__ void ln1_kernel(const float* __restrict__ x,
                           const float* __restrict__ gam,
                           const float* __restrict__ bet,
                           float* __restrict__ xp, float* __restrict__ tn)
{
    int warp = (blockIdx.x * blockDim.x + threadIdx.x) >> 5;
    if (warp >= NTOK) return;
    int lane = threadIdx.x & 31;
    int b  = warp / HWW;
    int hw = warp - b * HWW;
    const float* xb = x + (size_t)b * CC * HWW + hw;

    float v[12];
#pragma unroll
    for (int i = 0; i < 12; i++) v[i] = xb[(size_t)(lane + 32 * i) * HWW];
    float s = 0.f;
#pragma unroll
    for (int i = 0; i < 12; i++) s += v[i];
#pragma unroll
    for (int o = 16; o; o >>= 1) s += __shfl_xor_sync(0xffffffffu, s, o);
    float mu = s * (1.0f / CC);
    float q = 0.f;
#pragma unroll
    for (int i = 0; i < 12; i++) { float d = v[i] - mu; q += d * d; }
#pragma unroll
    for (int o = 16; o; o >>= 1) q += __shfl_xor_sync(0xffffffffu, q, o);
    float rs = rsqrtf(q * (1.0f / CC) + EPSV);
    size_t base = (size_t)warp * CC;
#pragma unroll
    for (int i = 0; i < 12; i++) {
        int c = lane + 32 * i;
        xp[base + c] = v[i];
        tn[base + c] = (v[i] - mu) * rs * gam[c] + bet[c];
    }
}

__global__ void ln2_kernel(const float* __restrict__ res,
                           const float* __restrict__ gam,
                           const float* __restrict__ bet,
                           float* __restrict__ outp)
{
    int warp = (blockIdx.x * blockDim.x + threadIdx.x) >> 5;
    if (warp >= NTOK) return;
    int lane = threadIdx.x & 31;
    size_t base = (size_t)warp * CC;
    float v[12];
#pragma unroll
    for (int i = 0; i < 12; i++) v[i] = res[base + lane + 32 * i];
    float s = 0.f;
#pragma unroll
    for (int i = 0; i < 12; i++) s += v[i];
#pragma unroll
    for (int o = 16; o; o >>= 1) s += __shfl_xor_sync(0xffffffffu, s, o);
    float mu = s * (1.0f / CC);
    float q = 0.f;
#pragma unroll
    for (int i = 0; i < 12; i++) { float d = v[i] - mu; q += d * d; }
#pragma unroll
    for (int o = 16; o; o >>= 1) q += __shfl_xor_sync(0xffffffffu, q, o);
    float rs = rsqrtf(q * (1.0f / CC) + EPSV);
#pragma unroll
    for (int i = 0; i < 12; i++) {
        int c = lane + 32 * i;
        outp[base + c] = (v[i] - mu) * rs * gam[c] + bet[c];
    }
}

// ---------------- DCNv4 sampling: one block per token, warp = group -------
__global__ __launch_bounds__(384) void dcn_kernel(
    const float* __restrict__ val,
    const float* __restrict__ om,
    float* __restrict__ outp)
{
    __shared__ float s_om[OMC];
    const int n = blockIdx.x;
    const int tid = threadIdx.x;
    if (tid < OMC) s_om[tid] = om[(size_t)n * OMC + tid];
    __syncthreads();

    const int g = tid >> 5, lane = tid & 31;
    const int b = n / HWW;
    const int hw = n - b * HWW;
    const int ii = hw / WW;
    const int jj = hw - ii * WW;

    const float* omb = s_om + g * 27;
    const float* vb  = val + b * (HWW * CC) + g * GCH + lane;

    float acc = 0.f;
#pragma unroll
    for (int k = 0; k < KK2; k++) {
        float dx = omb[2 * k];
        float dy = omb[2 * k + 1];
        float mk = omb[18 + k];
        float px = (float)jj + (float)(k % 3 - 1) + dx;
        float py = (float)ii + (float)(k / 3 - 1) + dy;
        float x0f = floorf(px), y0f = floorf(py);
        float tx = px - x0f, ty = py - y0f;
        int x0 = (int)x0f, y0 = (int)y0f;
        int x1 = x0 + 1,   y1 = y0 + 1;
        bool vx0 = (x0 >= 0) & (x0 < WW);
        bool vx1 = (x1 >= 0) & (x1 < WW);
        bool vy0 = (y0 >= 0) & (y0 < HH);
        bool vy1 = (y1 >= 0) & (y1 < HH);
        int row0 = y0 * (WW * CC), row1 = row0 + WW * CC;
        float v00 = (vy0 && vx0) ? __ldg(vb + row0 + x0 * CC) : 0.f;
        float v01 = (vy0 && vx1) ? __ldg(vb + row0 + x1 * CC) : 0.f;
        float v10 = (vy1 && vx0) ? __ldg(vb + row1 + x0 * CC) : 0.f;
        float v11 = (vy1 && vx1) ? __ldg(vb + row1 + x1 * CC) : 0.f;
        float top = v00 * (1.f - tx) + v01 * tx;
        float bot = v10 * (1.f - tx) + v11 * tx;
        acc += mk * (top * (1.f - ty) + bot * ty);
    }
    outp[n * CC + g * GCH + lane] = acc;
}

// ---------------- final transpose ----------------
__global__ void transpose_out(const float* __restrict__ fin,
                              float* __restrict__ outp)
{
    __shared__ float s[32][33];
    int b   = blockIdx.z;
    int hw0 = blockIdx.x * 32;
    int c0  = blockIdx.y * 32;
    int tx = threadIdx.x, ty = threadIdx.y;
#pragma unroll
    for (int r = 0; r < 4; r++) {
        int hw = hw0 + ty + 8 * r;
        s[ty + 8 * r][tx] = fin[(size_t)(b * HWW + hw) * CC + c0 + tx];
    }
    __syncthreads();
#pragma unroll
    for (int r = 0; r < 4; r++) {
        int c = c0 + ty + 8 * r;
        outp[(size_t)(b * CC + c) * HWW + hw0 + tx] = s[tx][ty + 8 * r];
    }
}

// --------------------------------------------------------------------------
extern "C" void kernel_launch(void* const* d_in, const int* in_sizes, int n_in,
                              void* d_out, int out_size)
{
    const float* x       = (const float*)d_in[0];
    const float* ln1_g   = (const float*)d_in[1];
    const float* ln1_b   = (const float*)d_in[2];
    const float* vproj_w = (const float*)d_in[3];
    const float* vproj_b = (const float*)d_in[4];
    const float* om_w    = (const float*)d_in[5];
    const float* om_b    = (const float*)d_in[6];
    const float* oproj_w = (const float*)d_in[7];
    const float* oproj_b = (const float*)d_in[8];
    const float* ln2_g   = (const float*)d_in[9];
    const float* ln2_b   = (const float*)d_in[10];
    const float* fc1_w   = (const float*)d_in[11];
    const float* fc1_b   = (const float*)d_in[12];
    const float* fc2_w   = (const float*)d_in[13];
    const float* fc2_b   = (const float*)d_in[14];
    float* outp = (float*)d_out;

    float *xp, *tn, *val, *om, *dcn, *res, *ln2o, *hid, *fin, *wm;
    cudaGetSymbolAddress((void**)&xp,  g_xp);
    cudaGetSymbolAddress((void**)&tn,  g_tn);
    cudaGetSymbolAddress((void**)&val, g_val);
    cudaGetSymbolAddress((void**)&om,  g_om);
    cudaGetSymbolAddress((void**)&dcn, g_dcn);
    cudaGetSymbolAddress((void**)&res, g_res);
    cudaGetSymbolAddress((void**)&ln2o, g_ln2);
    cudaGetSymbolAddress((void**)&hid, g_hid);
    cudaGetSymbolAddress((void**)&fin, g_fin);
    cudaGetSymbolAddress((void**)&wm,  g_wm);

    static int attr_done = 0;
    if (!attr_done) {
        cudaFuncSetAttribute(gemm_mma<0>, cudaFuncAttributeMaxDynamicSharedMemorySize, GEMM_SMEM_BYTES);
        cudaFuncSetAttribute(gemm_mma<1>, cudaFuncAttributeMaxDynamicSharedMemorySize, GEMM_SMEM_BYTES);
        cudaFuncSetAttribute(gemm_mma<2>, cudaFuncAttributeMaxDynamicSharedMemorySize, GEMM_SMEM_BYTES);
        attr_done = 1;
    }

    // pad om_w to [384][384]
    pad_om<<<CC, CC>>>(om_w, wm);
    // 1. transpose + LN1
    ln1_kernel<<<NTOK / 8, 256>>>(x, ln1_g, ln1_b, xp, tn);
    // 2. val = tn @ vproj_w + b
    gemm_mma<0><<<dim3(NTOK / 128, 3), 256, GEMM_SMEM_BYTES>>>(tn, vproj_w, vproj_b, nullptr, val, CC, CC, CC);
    // 3. om = tn @ om_w + b (padded W, Nn=324)
    gemm_mma<0><<<dim3(NTOK / 128, 3), 256, GEMM_SMEM_BYTES>>>(tn, wm, om_b, nullptr, om, OMC, CC, CC);
    // 4. DCN sampling
    dcn_kernel<<<NTOK, 384>>>(val, om, dcn);
    // 5. res = xp + dcn @ oproj_w + b
    gemm_mma<2><<<dim3(NTOK / 128, 3), 256, GEMM_SMEM_BYTES>>>(dcn, oproj_w, oproj_b, xp, res, CC, CC, CC);
    // 6. LN2
    ln2_kernel<<<NTOK / 8, 256>>>(res, ln2_g, ln2_b, ln2o);
    // 7. hid = gelu(ln2o @ fc1_w + b)
    gemm_mma<1><<<dim3(NTOK / 128, HID / 128), 256, GEMM_SMEM_BYTES>>>(ln2o, fc1_w, fc1_b, nullptr, hid, HID, HID, CC);
    // 8. fin = res + hid @ fc2_w + b
    gemm_mma<2><<<dim3(NTOK / 128, 3), 256, GEMM_SMEM_BYTES>>>(hid, fc2_w, fc2_b, res, fin, CC, CC, HID);
    // 9. transpose back
    transpose_out<<<dim3(HWW / 32, CC / 32, BB), dim3(32, 8)>>>(fin, outp);
}